// round 8
// baseline (speedup 1.0000x reference)
#include <cuda_runtime.h>
#include <cstdint>
#include <cstddef>

// Problem constants
#define BATCH 512
#define SEQ   256
#define XD    512
#define HD    1024
#define KTOT  (HD + XD)   // 1536

// GEMM tiling
#define MT   64
#define NT   64
#define KT   32
#define SSTR 36            // KT + 4 pad: conflict-free smem rows
#define NKT  (KTOT / KT)   // 48
#define THREADS 512
#define NSTAGE 4
#define SMEM_BYTES (NSTAGE * 2 * MT * SSTR * 4)   // 73728

// Static device scratch (allocation-free rule)
__device__ float g_W[HD * KTOT];              // prepacked tf32-rounded [W_hh | W_xh]
__device__ float g_X[BATCH * SEQ * XD];       // tf32-rounded copy of X
__device__ float g_H[2][BATCH * HD];          // ping-pong hidden state

__device__ __forceinline__ float tf32r(float x) {
    uint32_t u;
    asm("cvt.rna.tf32.f32 %0, %1;" : "=r"(u) : "f"(x));
    return __uint_as_float(u);
}

#define MMA_TF32(c, a, b)                                                   \
    asm volatile(                                                           \
        "mma.sync.aligned.m16n8k8.row.col.f32.tf32.tf32.f32 "               \
        "{%0,%1,%2,%3}, {%4,%5,%6,%7}, {%8,%9}, {%0,%1,%2,%3};\n"           \
        : "+f"((c)[0]), "+f"((c)[1]), "+f"((c)[2]), "+f"((c)[3])            \
        : "r"((a)[0]), "r"((a)[1]), "r"((a)[2]), "r"((a)[3]),               \
          "r"((b)[0]), "r"((b)[1]))

__device__ __forceinline__ void cp16(void* smem_dst, const void* gsrc) {
    uint32_t s = (uint32_t)__cvta_generic_to_shared(smem_dst);
    asm volatile("cp.async.cg.shared.global [%0], [%1], 16;\n" :: "r"(s), "l"(gsrc));
}
__device__ __forceinline__ void cp_commit() {
    asm volatile("cp.async.commit_group;\n" ::: "memory");
}
template <int N>
__device__ __forceinline__ void cp_wait() {
    asm volatile("cp.async.wait_group %0;\n" :: "n"(N) : "memory");
}

// ---------------------------------------------------------------------------
// Prep kernels
// ---------------------------------------------------------------------------
__global__ void pack_w_kernel(const float* __restrict__ Whh,
                              const float* __restrict__ Wxh) {
    int idx = blockIdx.x * 256 + threadIdx.x;
    if (idx >= HD * KTOT) return;
    int n = idx / KTOT;
    int k = idx - n * KTOT;
    float v = (k < HD) ? Whh[n * HD + k] : Wxh[n * XD + (k - HD)];
    g_W[idx] = tf32r(v);
}

__global__ void pack_x_kernel(const float* __restrict__ X) {
    int idx = blockIdx.x * 256 + threadIdx.x;
    g_X[idx] = tf32r(X[idx]);
}

__global__ void zero_kernel() {
    g_H[0][blockIdx.x * 1024 + threadIdx.x] = 0.0f;
}

// ---------------------------------------------------------------------------
// One recurrence step. CTA tile 64x64, 512 threads = 16 warps:
// (warpM 2) x (warpN 2) x (warpK 4); warp tile 32x32, 8-wide k-slice/stage.
// 4-stage cp.async ring + REGISTER-LEVEL fragment double buffering:
// LDS(kt+1) issues before MMA(kt) so fragment-load latency overlaps compute.
// ---------------------------------------------------------------------------
template <bool SIG>
__global__ __launch_bounds__(THREADS, 1)
void step_kernel(const float* __restrict__ bias, int t) {
    extern __shared__ __align__(16) float S[];   // [NSTAGE][2][MT][SSTR]

    const float* __restrict__ Hin  = g_H[t & 1];
    float* __restrict__       Hout = g_H[(t + 1) & 1];

    const int tid   = threadIdx.x;
    const int mBase = blockIdx.y * MT;
    const int nBase = blockIdx.x * NT;
    const int lane  = tid & 31;
    const int warp  = tid >> 5;          // 0..15
    const int warpK = warp >> 2;         // 0..3  -> k-slice
    const int warpM = (warp >> 1) & 1;   // 0..1
    const int warpN = warp & 1;          // 0..1
    const int g     = lane >> 2;         // 0..7
    const int tig   = lane & 3;          // 0..3
    const int ldRow = tid >> 3;          // 0..63
    const int ldCol = (tid & 7) * 4;     // 0..28

    float acc[2][4][4];
#pragma unroll
    for (int mi = 0; mi < 2; mi++)
#pragma unroll
        for (int ni = 0; ni < 4; ni++)
#pragma unroll
            for (int r = 0; r < 4; r++) acc[mi][ni][r] = 0.0f;

    auto stile = [&](int st, int ab) -> float* {
        return S + ((st * 2 + ab) * MT) * SSTR;
    };

    auto issue = [&](int kt) {
        const int kBase = kt * KT;
        const int st = kt & (NSTAGE - 1);
        const float* aSrc;
        if (kBase < HD) {
            aSrc = Hin + (size_t)(mBase + ldRow) * HD + kBase + ldCol;
        } else {
            aSrc = g_X + (size_t)(mBase + ldRow) * (SEQ * XD) + (size_t)t * XD
                       + (kBase - HD) + ldCol;
        }
        cp16(stile(st, 0) + ldRow * SSTR + ldCol, aSrc);
        cp16(stile(st, 1) + ldRow * SSTR + ldCol,
             g_W + (size_t)(nBase + ldRow) * KTOT + kBase + ldCol);
        cp_commit();
    };

    const int k0 = warpK * 8;

    // Fragment registers: ping-pong sets
    uint32_t afr[2][2][4];
    uint32_t bfr[2][4][2];

    auto lds_frags = [&](int kt, int sel) {
        const int st = kt & (NSTAGE - 1);
        const float* As = stile(st, 0);
        const float* Bs = stile(st, 1);
#pragma unroll
        for (int mi = 0; mi < 2; mi++) {
            const int r0 = warpM * 32 + mi * 16 + g;
            afr[sel][mi][0] = __float_as_uint(As[r0 * SSTR + k0 + tig]);
            afr[sel][mi][1] = __float_as_uint(As[(r0 + 8) * SSTR + k0 + tig]);
            afr[sel][mi][2] = __float_as_uint(As[r0 * SSTR + k0 + 4 + tig]);
            afr[sel][mi][3] = __float_as_uint(As[(r0 + 8) * SSTR + k0 + 4 + tig]);
        }
#pragma unroll
        for (int ni = 0; ni < 4; ni++) {
            const int c0 = warpN * 32 + ni * 8 + g;
            bfr[sel][ni][0] = __float_as_uint(Bs[c0 * SSTR + k0 + tig]);
            bfr[sel][ni][1] = __float_as_uint(Bs[c0 * SSTR + k0 + 4 + tig]);
        }
    };

    // Prologue: fill 3 ring slots, preload fragments of stage 0
    issue(0); issue(1); issue(2);
    cp_wait<2>();          // stage 0 arrived (for this thread)
    __syncthreads();       // visible to all warps
    lds_frags(0, 0);

#pragma unroll 2
    for (int kt = 0; kt < NKT; kt++) {
        const int sel = kt & 1;

        if (kt + 1 < NKT) {
            // Ensure stage kt+1 arrived (<=1 group may remain outstanding)
            if (kt + 2 < NKT) cp_wait<1>();
            else              cp_wait<0>();
            __syncthreads();              // publish kt+1; license slot reuse
            if (kt + 3 < NKT) issue(kt + 3);
            lds_frags(kt + 1, sel ^ 1);   // LDS overlaps the MMAs below
        }

#pragma unroll
        for (int mi = 0; mi < 2; mi++)
#pragma unroll
            for (int ni = 0; ni < 4; ni++)
                MMA_TF32(acc[mi][ni], afr[sel][mi], bfr[sel][ni]);
    }
    __syncthreads();   // all stages consumed; S becomes reduction scratch

    // ---- Reduce 4 warpK partials through smem (conflict-free: stride 36) ----
    float* Red = S;
    const int grp = warpM * 2 + warpN;
    const int base0 = (0 * 4 + grp) * (32 * 36) + lane * 36;
    const int base1 = (1 * 4 + grp) * (32 * 36) + lane * 36;

    if (warpK == 1 || warpK == 3) {
        const int b = (warpK == 1) ? base0 : base1;
#pragma unroll
        for (int mi = 0; mi < 2; mi++)
#pragma unroll
            for (int ni = 0; ni < 4; ni++)
                *(float4*)&Red[b + mi * 16 + ni * 4] =
                    make_float4(acc[mi][ni][0], acc[mi][ni][1],
                                acc[mi][ni][2], acc[mi][ni][3]);
    }
    __syncthreads();
    if (warpK == 0 || warpK == 2) {
        const int b = (warpK == 0) ? base0 : base1;
#pragma unroll
        for (int mi = 0; mi < 2; mi++)
#pragma unroll
            for (int ni = 0; ni < 4; ni++) {
                float4 v = *(float4*)&Red[b + mi * 16 + ni * 4];
                acc[mi][ni][0] += v.x; acc[mi][ni][1] += v.y;
                acc[mi][ni][2] += v.z; acc[mi][ni][3] += v.w;
            }
        if (warpK == 2) {
#pragma unroll
            for (int mi = 0; mi < 2; mi++)
#pragma unroll
                for (int ni = 0; ni < 4; ni++)
                    *(float4*)&Red[base1 + mi * 16 + ni * 4] =
                        make_float4(acc[mi][ni][0], acc[mi][ni][1],
                                    acc[mi][ni][2], acc[mi][ni][3]);
        }
    }
    __syncthreads();
    if (warpK != 0) return;

#pragma unroll
    for (int mi = 0; mi < 2; mi++)
#pragma unroll
        for (int ni = 0; ni < 4; ni++) {
            float4 v = *(float4*)&Red[base1 + mi * 16 + ni * 4];
            acc[mi][ni][0] += v.x; acc[mi][ni][1] += v.y;
            acc[mi][ni][2] += v.z; acc[mi][ni][3] += v.w;
        }

    // ---- Epilogue: bias + (optional) sigmoid + tf32 rounding ----
    const int rBase = mBase + warpM * 32;
    const int cBase = nBase + warpN * 32;
#pragma unroll
    for (int mi = 0; mi < 2; mi++) {
#pragma unroll
        for (int ni = 0; ni < 4; ni++) {
            const int c  = cBase + ni * 8 + 2 * tig;
            const float b0 = bias[c];
            const float b1 = bias[c + 1];
            const int r0 = rBase + mi * 16 + g;
            float z0 = acc[mi][ni][0] + b0;
            float z1 = acc[mi][ni][1] + b1;
            float z2 = acc[mi][ni][2] + b0;
            float z3 = acc[mi][ni][3] + b1;
            if (SIG) {
                z0 = tf32r(1.0f / (1.0f + __expf(-z0)));
                z1 = tf32r(1.0f / (1.0f + __expf(-z1)));
                z2 = tf32r(1.0f / (1.0f + __expf(-z2)));
                z3 = tf32r(1.0f / (1.0f + __expf(-z3)));
            }
            *(float2*)&Hout[(size_t)r0 * HD + c]       = make_float2(z0, z1);
            *(float2*)&Hout[(size_t)(r0 + 8) * HD + c] = make_float2(z2, z3);
        }
    }
}

// ---------------------------------------------------------------------------
// Final: out[b] = H_final[b] . W_hy  (fp32, one warp per row)
// ---------------------------------------------------------------------------
__global__ void out_kernel(const float* __restrict__ Why, float* __restrict__ out) {
    const int warp = threadIdx.x >> 5;
    const int lane = threadIdx.x & 31;
    const int row  = blockIdx.x * 4 + warp;
    const float* h = g_H[0] + (size_t)row * HD;   // after 256 steps -> buffer 0
    float s = 0.0f;
    for (int n = lane; n < HD; n += 32) s += h[n] * Why[n];
#pragma unroll
    for (int o = 16; o; o >>= 1) s += __shfl_xor_sync(0xFFFFFFFFu, s, o);
    if (lane == 0) out[row] = s;
}

// ---------------------------------------------------------------------------
extern "C" void kernel_launch(void* const* d_in, const int* in_sizes, int n_in,
                              void* d_out, int out_size) {
    const float* X    = (const float*)d_in[0];   // [512, 256, 512]
    const float* Whh  = (const float*)d_in[1];   // [1024, 1024]
    const float* Wxh  = (const float*)d_in[2];   // [1024, 512]
    const float* Why  = (const float*)d_in[3];   // [1024]
    const float* bias = (const float*)d_in[4];   // [1024]
    float* out = (float*)d_out;                  // [512]

    cudaFuncSetAttribute(step_kernel<true>,
                         cudaFuncAttributeMaxDynamicSharedMemorySize, SMEM_BYTES);
    cudaFuncSetAttribute(step_kernel<false>,
                         cudaFuncAttributeMaxDynamicSharedMemorySize, SMEM_BYTES);

    pack_w_kernel<<<(HD * KTOT + 255) / 256, 256>>>(Whh, Wxh);
    pack_x_kernel<<<(BATCH * SEQ * XD) / 256, 256>>>(X);
    zero_kernel<<<BATCH, 1024>>>();

    dim3 grid(HD / NT, BATCH / MT);  // (16, 8) = 128 CTAs, 512 threads each
    for (int t = 0; t < SEQ - 1; ++t)
        step_kernel<true><<<grid, THREADS, SMEM_BYTES>>>(bias, t);
    step_kernel<false><<<grid, THREADS, SMEM_BYTES>>>(bias, SEQ - 1);

    out_kernel<<<BATCH / 4, 128>>>(Why, out);
}

// round 9
// speedup vs baseline: 1.1296x; 1.1296x over previous
#include <cuda_runtime.h>
#include <cstdint>
#include <cstddef>

// Problem constants
#define BATCH 512
#define SEQ   256
#define XD    512
#define HD    1024
#define KTOT  (HD + XD)   // 1536

// GEMM tiling
#define MT   64
#define NT   64
#define KT   32
#define SSTR 36            // KT + 4 pad: conflict-free smem rows
#define NKT  (KTOT / KT)   // 48
#define THREADS 512
#define NS   6             // mbarrier ring stages
#define LEAD 3             // production lead (stages of prefetch); skew tol = NS-LEAD
#define STAGE_FLOATS (2 * MT * SSTR)               // 4608 floats = 18432 B
#define SMEM_BYTES (NS * STAGE_FLOATS * 4)         // 110592 B

// Static device scratch (allocation-free rule)
__device__ float g_W[HD * KTOT];              // prepacked tf32-rounded [W_hh | W_xh]
__device__ float g_X[BATCH * SEQ * XD];       // tf32-rounded copy of X
__device__ float g_H[2][BATCH * HD];          // ping-pong hidden state

__device__ __forceinline__ float tf32r(float x) {
    uint32_t u;
    asm("cvt.rna.tf32.f32 %0, %1;" : "=r"(u) : "f"(x));
    return __uint_as_float(u);
}

__device__ __forceinline__ uint32_t smem_u32(const void* p) {
    return (uint32_t)__cvta_generic_to_shared(p);
}

#define MMA_TF32(c, a, b)                                                   \
    asm volatile(                                                           \
        "mma.sync.aligned.m16n8k8.row.col.f32.tf32.tf32.f32 "               \
        "{%0,%1,%2,%3}, {%4,%5,%6,%7}, {%8,%9}, {%0,%1,%2,%3};\n"           \
        : "+f"((c)[0]), "+f"((c)[1]), "+f"((c)[2]), "+f"((c)[3])            \
        : "r"((a)[0]), "r"((a)[1]), "r"((a)[2]), "r"((a)[3]),               \
          "r"((b)[0]), "r"((b)[1]))

__device__ __forceinline__ void cp16(void* smem_dst, const void* gsrc) {
    uint32_t s = (uint32_t)__cvta_generic_to_shared(smem_dst);
    asm volatile("cp.async.cg.shared.global [%0], [%1], 16;\n" :: "r"(s), "l"(gsrc));
}

#define MBARRIER_INIT(a, c) \
    asm volatile("mbarrier.init.shared.b64 [%0], %1;" :: "r"(a), "r"((uint32_t)(c)) : "memory")
#define MBARRIER_ARRIVE(a) \
    asm volatile("mbarrier.arrive.shared.b64 _, [%0];" :: "r"(a) : "memory")
#define CP_MBAR_ARRIVE(a) \
    asm volatile("cp.async.mbarrier.arrive.noinc.shared.b64 [%0];" :: "r"(a) : "memory")

#define MBARRIER_WAIT_PARITY(mbar_addr, phase) do {                              \
    uint32_t _m = (mbar_addr), _p = (phase), _d;                                 \
    asm volatile("{\n\t.reg .pred p;\n\t"                                        \
        "mbarrier.try_wait.parity.acquire.cta.shared::cta.b64 p, [%1], %2;\n\t"  \
        "selp.b32 %0, 1, 0, p;\n\t}" : "=r"(_d) : "r"(_m), "r"(_p) : "memory");  \
    if (!_d) {                                                                   \
        asm volatile("{\n\t.reg .pred P1;\n\t"                                   \
            "WL_%=:\n\t"                                                         \
            "mbarrier.try_wait.parity.acquire.cta.shared::cta.b64 P1, [%0], %1, 0x989680;\n\t" \
            "@P1 bra.uni WD_%=;\n\t"                                             \
            "bra.uni WL_%=;\n\t"                                                 \
            "WD_%=:\n\t}" :: "r"(_m), "r"(_p) : "memory");                       \
    }                                                                            \
} while (0)

// ---------------------------------------------------------------------------
// Prep kernels
// ---------------------------------------------------------------------------
__global__ void pack_w_kernel(const float* __restrict__ Whh,
                              const float* __restrict__ Wxh) {
    int idx = blockIdx.x * 256 + threadIdx.x;
    if (idx >= HD * KTOT) return;
    int n = idx / KTOT;
    int k = idx - n * KTOT;
    float v = (k < HD) ? Whh[n * HD + k] : Wxh[n * XD + (k - HD)];
    g_W[idx] = tf32r(v);
}

__global__ void pack_x_kernel(const float* __restrict__ X) {
    int idx = blockIdx.x * 256 + threadIdx.x;
    g_X[idx] = tf32r(X[idx]);
}

__global__ void zero_kernel() {
    g_H[0][blockIdx.x * 1024 + threadIdx.x] = 0.0f;
}

// ---------------------------------------------------------------------------
// One recurrence step. CTA tile 64x64, 512 threads = 16 warps:
// (warpM 2) x (warpN 2) x (warpK 4); warp tile 32x32, 8-wide k-slice/stage.
// NS=6 mbarrier ring (full: cp.async.mbarrier.arrive x512, empty: 16 warps),
// production lead 3 stages: NO __syncthreads in the main loop -> warps
// free-run with up to 3 stages of skew; L2 bursts amortize across the ring.
// ---------------------------------------------------------------------------
template <bool SIG>
__global__ __launch_bounds__(THREADS, 1)
void step_kernel(const float* __restrict__ bias, int t) {
    extern __shared__ __align__(16) float S[];   // [NS][2][MT][SSTR]
    __shared__ __align__(8) uint64_t mb_full[NS], mb_empty[NS];

    const float* __restrict__ Hin  = g_H[t & 1];
    float* __restrict__       Hout = g_H[(t + 1) & 1];

    const int tid   = threadIdx.x;
    const int mBase = blockIdx.y * MT;
    const int nBase = blockIdx.x * NT;
    const int lane  = tid & 31;
    const int warp  = tid >> 5;          // 0..15
    const int warpK = warp >> 2;         // 0..3  -> k-slice
    const int warpM = (warp >> 1) & 1;   // 0..1
    const int warpN = warp & 1;          // 0..1
    const int g     = lane >> 2;         // 0..7
    const int tig   = lane & 3;          // 0..3
    const int ldRow = tid >> 3;          // 0..63
    const int ldCol = (tid & 7) * 4;     // 0..28

    if (tid == 0) {
        for (int s = 0; s < NS; s++) {
            MBARRIER_INIT(smem_u32(&mb_full[s]), THREADS);  // 512 cp.async arrivals
            MBARRIER_INIT(smem_u32(&mb_empty[s]), 16);      // one per warp
        }
    }
    __syncthreads();

    float acc[2][4][4];
#pragma unroll
    for (int mi = 0; mi < 2; mi++)
#pragma unroll
        for (int ni = 0; ni < 4; ni++)
#pragma unroll
            for (int r = 0; r < 4; r++) acc[mi][ni][r] = 0.0f;

    auto stile = [&](int st, int ab) -> float* {
        return S + (st * 2 + ab) * (MT * SSTR);
    };

    auto issue = [&](int kt) {
        const int kBase = kt * KT;
        const int st = kt % NS;
        const float* aSrc;
        if (kBase < HD) {
            aSrc = Hin + (size_t)(mBase + ldRow) * HD + kBase + ldCol;
        } else {
            aSrc = g_X + (size_t)(mBase + ldRow) * (SEQ * XD) + (size_t)t * XD
                       + (kBase - HD) + ldCol;
        }
        cp16(stile(st, 0) + ldRow * SSTR + ldCol, aSrc);
        cp16(stile(st, 1) + ldRow * SSTR + ldCol,
             g_W + (size_t)(nBase + ldRow) * KTOT + kBase + ldCol);
        CP_MBAR_ARRIVE(smem_u32(&mb_full[st]));
    };

    // Prologue: produce stages 0..LEAD-1 (first uses of slots 0..2, no empty wait)
#pragma unroll
    for (int p = 0; p < LEAD; p++) issue(p);

    const int k0 = warpK * 8;

    for (int kt = 0; kt < NKT; kt++) {
        const int j  = kt / NS;
        const int st = kt - j * NS;

        // --- consume stage kt ---
        MBARRIER_WAIT_PARITY(smem_u32(&mb_full[st]), j & 1);

        const float* As = stile(st, 0);
        const float* Bs = stile(st, 1);
        uint32_t af[2][4];
#pragma unroll
        for (int mi = 0; mi < 2; mi++) {
            const int r0 = warpM * 32 + mi * 16 + g;
            af[mi][0] = __float_as_uint(As[r0 * SSTR + k0 + tig]);
            af[mi][1] = __float_as_uint(As[(r0 + 8) * SSTR + k0 + tig]);
            af[mi][2] = __float_as_uint(As[r0 * SSTR + k0 + 4 + tig]);
            af[mi][3] = __float_as_uint(As[(r0 + 8) * SSTR + k0 + 4 + tig]);
        }
        uint32_t bf[4][2];
#pragma unroll
        for (int ni = 0; ni < 4; ni++) {
            const int c0 = warpN * 32 + ni * 8 + g;
            bf[ni][0] = __float_as_uint(Bs[c0 * SSTR + k0 + tig]);
            bf[ni][1] = __float_as_uint(Bs[c0 * SSTR + k0 + 4 + tig]);
        }
#pragma unroll
        for (int mi = 0; mi < 2; mi++)
#pragma unroll
            for (int ni = 0; ni < 4; ni++)
                MMA_TF32(acc[mi][ni], af[mi], bf[ni]);

        if (lane == 0) MBARRIER_ARRIVE(smem_u32(&mb_empty[st]));

        // --- produce stage kt+LEAD ---
        const int pk = kt + LEAD;
        if (pk < NKT) {
            const int pj = pk / NS;
            const int ps = pk - pj * NS;
            if (pk >= NS)   // slot's previous use (stage pk-NS) must be drained
                MBARRIER_WAIT_PARITY(smem_u32(&mb_empty[ps]), (pj - 1) & 1);
            issue(pk);
        }
    }
    __syncthreads();   // all stages consumed; S becomes reduction scratch

    // ---- Reduce 4 warpK partials through smem (conflict-free: stride 36) ----
    float* Red = S;
    const int grp = warpM * 2 + warpN;
    const int base0 = (0 * 4 + grp) * (32 * 36) + lane * 36;
    const int base1 = (1 * 4 + grp) * (32 * 36) + lane * 36;

    if (warpK == 1 || warpK == 3) {
        const int b = (warpK == 1) ? base0 : base1;
#pragma unroll
        for (int mi = 0; mi < 2; mi++)
#pragma unroll
            for (int ni = 0; ni < 4; ni++)
                *(float4*)&Red[b + mi * 16 + ni * 4] =
                    make_float4(acc[mi][ni][0], acc[mi][ni][1],
                                acc[mi][ni][2], acc[mi][ni][3]);
    }
    __syncthreads();
    if (warpK == 0 || warpK == 2) {
        const int b = (warpK == 0) ? base0 : base1;
#pragma unroll
        for (int mi = 0; mi < 2; mi++)
#pragma unroll
            for (int ni = 0; ni < 4; ni++) {
                float4 v = *(float4*)&Red[b + mi * 16 + ni * 4];
                acc[mi][ni][0] += v.x; acc[mi][ni][1] += v.y;
                acc[mi][ni][2] += v.z; acc[mi][ni][3] += v.w;
            }
        if (warpK == 2) {
#pragma unroll
            for (int mi = 0; mi < 2; mi++)
#pragma unroll
                for (int ni = 0; ni < 4; ni++)
                    *(float4*)&Red[base1 + mi * 16 + ni * 4] =
                        make_float4(acc[mi][ni][0], acc[mi][ni][1],
                                    acc[mi][ni][2], acc[mi][ni][3]);
        }
    }
    __syncthreads();
    if (warpK != 0) return;

#pragma unroll
    for (int mi = 0; mi < 2; mi++)
#pragma unroll
        for (int ni = 0; ni < 4; ni++) {
            float4 v = *(float4*)&Red[base1 + mi * 16 + ni * 4];
            acc[mi][ni][0] += v.x; acc[mi][ni][1] += v.y;
            acc[mi][ni][2] += v.z; acc[mi][ni][3] += v.w;
        }

    // ---- Epilogue: bias + (optional) sigmoid + tf32 rounding ----
    const int rBase = mBase + warpM * 32;
    const int cBase = nBase + warpN * 32;
#pragma unroll
    for (int mi = 0; mi < 2; mi++) {
#pragma unroll
        for (int ni = 0; ni < 4; ni++) {
            const int c  = cBase + ni * 8 + 2 * tig;
            const float b0 = bias[c];
            const float b1 = bias[c + 1];
            const int r0 = rBase + mi * 16 + g;
            float z0 = acc[mi][ni][0] + b0;
            float z1 = acc[mi][ni][1] + b1;
            float z2 = acc[mi][ni][2] + b0;
            float z3 = acc[mi][ni][3] + b1;
            if (SIG) {
                z0 = tf32r(1.0f / (1.0f + __expf(-z0)));
                z1 = tf32r(1.0f / (1.0f + __expf(-z1)));
                z2 = tf32r(1.0f / (1.0f + __expf(-z2)));
                z3 = tf32r(1.0f / (1.0f + __expf(-z3)));
            }
            *(float2*)&Hout[(size_t)r0 * HD + c]       = make_float2(z0, z1);
            *(float2*)&Hout[(size_t)(r0 + 8) * HD + c] = make_float2(z2, z3);
        }
    }
}

// ---------------------------------------------------------------------------
// Final: out[b] = H_final[b] . W_hy  (fp32, one warp per row)
// ---------------------------------------------------------------------------
__global__ void out_kernel(const float* __restrict__ Why, float* __restrict__ out) {
    const int warp = threadIdx.x >> 5;
    const int lane = threadIdx.x & 31;
    const int row  = blockIdx.x * 4 + warp;
    const float* h = g_H[0] + (size_t)row * HD;   // after 256 steps -> buffer 0
    float s = 0.0f;
    for (int n = lane; n < HD; n += 32) s += h[n] * Why[n];
#pragma unroll
    for (int o = 16; o; o >>= 1) s += __shfl_xor_sync(0xFFFFFFFFu, s, o);
    if (lane == 0) out[row] = s;
}

// ---------------------------------------------------------------------------
extern "C" void kernel_launch(void* const* d_in, const int* in_sizes, int n_in,
                              void* d_out, int out_size) {
    const float* X    = (const float*)d_in[0];   // [512, 256, 512]
    const float* Whh  = (const float*)d_in[1];   // [1024, 1024]
    const float* Wxh  = (const float*)d_in[2];   // [1024, 512]
    const float* Why  = (const float*)d_in[3];   // [1024]
    const float* bias = (const float*)d_in[4];   // [1024]
    float* out = (float*)d_out;                  // [512]

    cudaFuncSetAttribute(step_kernel<true>,
                         cudaFuncAttributeMaxDynamicSharedMemorySize, SMEM_BYTES);
    cudaFuncSetAttribute(step_kernel<false>,
                         cudaFuncAttributeMaxDynamicSharedMemorySize, SMEM_BYTES);

    pack_w_kernel<<<(HD * KTOT + 255) / 256, 256>>>(Whh, Wxh);
    pack_x_kernel<<<(BATCH * SEQ * XD) / 256, 256>>>(X);
    zero_kernel<<<BATCH, 1024>>>();

    dim3 grid(HD / NT, BATCH / MT);  // (16, 8) = 128 CTAs, 512 threads each
    for (int t = 0; t < SEQ - 1; ++t)
        step_kernel<true><<<grid, THREADS, SMEM_BYTES>>>(bias, t);
    step_kernel<false><<<grid, THREADS, SMEM_BYTES>>>(bias, SEQ - 1);

    out_kernel<<<BATCH / 4, 128>>>(Why, out);
}